// round 14
// baseline (speedup 1.0000x reference)
#include <cuda_runtime.h>
#include <cuda_fp16.h>
#include <cstdint>
#include <math.h>

#define B_   4
#define N_   1024
#define DM   512
#define H_   8
#define DH_  64
#define DI   2048
#define MROWS (B_*N_)          // 4096
#define QKV3 (3*DM)            // 1536

// ---------------------------------------------------------------------------
// Scratch (device globals)
// ---------------------------------------------------------------------------
__device__ __half g_Znh [MROWS*DM];
__device__ __half g_hq  [B_*H_*N_*DH_];
__device__ __half g_hk  [B_*H_*N_*DH_];
__device__ __half g_hvT [B_*H_*DH_*N_];
__device__ __half g_attnh[MROWS*DM];
__device__ float  g_Z2  [MROWS*DM];
__device__ __half g_Zn2h[MROWS*DM];
__device__ __half g_Hidh[MROWS*DI];
__device__ __half g_hWqkv[QKV3*DM];
__device__ __half g_hWo [DM*DM];
__device__ __half g_hWp1[DI*DM];
__device__ __half g_hWp2[DM*DI];
__device__ uint32_t g_bm[(size_t)B_*N_*N_];   // packed half2(nm - gamma*D, mask)

// ---------------------------------------------------------------------------
// Helpers
// ---------------------------------------------------------------------------
__device__ __forceinline__ uint32_t smem_u32(const void* p) {
    uint32_t a;
    asm("{ .reg .u64 t; cvta.to.shared.u64 t, %1; cvt.u32.u64 %0, t; }" : "=r"(a) : "l"(p));
    return a;
}
#define CP_ASYNC16(sa, ga) \
    asm volatile("cp.async.cg.shared.global [%0], [%1], 16;" :: "r"(sa), "l"(ga))
#define CP_COMMIT() asm volatile("cp.async.commit_group;" ::: "memory")
template<int Nw> __device__ __forceinline__ void cp_wait() {
    asm volatile("cp.async.wait_group %0;" :: "n"(Nw) : "memory");
}
#define LDSM_X4(r0, r1, r2, r3, addr) \
    asm volatile("ldmatrix.sync.aligned.m8n8.x4.shared.b16 {%0,%1,%2,%3}, [%4];" \
        : "=r"(r0), "=r"(r1), "=r"(r2), "=r"(r3) : "r"(addr))
__device__ __forceinline__ void mma_f16(float& c0, float& c1, float& c2, float& c3,
                                        uint32_t a0, uint32_t a1, uint32_t a2, uint32_t a3,
                                        uint32_t b0, uint32_t b1) {
    asm volatile(
        "mma.sync.aligned.m16n8k16.row.col.f32.f16.f16.f32 "
        "{%0,%1,%2,%3},{%4,%5,%6,%7},{%8,%9},{%0,%1,%2,%3};"
        : "+f"(c0), "+f"(c1), "+f"(c2), "+f"(c3)
        : "r"(a0), "r"(a1), "r"(a2), "r"(a3), "r"(b0), "r"(b1));
}

// ---------------------------------------------------------------------------
// Single-launch fp32->fp16 conversion of all 4 weight matrices
// ---------------------------------------------------------------------------
#define Q0 (QKV3*DM/4)
#define Q1 (DM*DM/4)
#define Q2 (DI*DM/4)
#define Q3 (DM*DI/4)
__global__ void f2h_all(const float* __restrict__ w0, const float* __restrict__ w1,
                        const float* __restrict__ w2, const float* __restrict__ w3)
{
    int i = blockIdx.x * 256 + threadIdx.x;
    const float* s; __half* d;
    if (i < Q0)                        { s = w0; d = g_hWqkv; }
    else if ((i -= Q0) < Q1)           { s = w1; d = g_hWo; }
    else if ((i -= Q1) < Q2)           { s = w2; d = g_hWp1; }
    else if ((i -= Q2) < Q3)           { s = w3; d = g_hWp2; }
    else return;
    float4 v = reinterpret_cast<const float4*>(s)[i];
    reinterpret_cast<__half2*>(d)[2 * i]     = __floats2half2_rn(v.x, v.y);
    reinterpret_cast<__half2*>(d)[2 * i + 1] = __floats2half2_rn(v.z, v.w);
}

// ---------------------------------------------------------------------------
// Precompute packed bias/mask: bm = half2(nm - gamma*D, mask)
// ---------------------------------------------------------------------------
__global__ void bm_kernel(const float* __restrict__ nm, const float* __restrict__ D,
                          const float* __restrict__ mask, const float* __restrict__ gptr)
{
    const int i = blockIdx.x * 256 + threadIdx.x;
    const float g = gptr[0];
    float4 a = reinterpret_cast<const float4*>(nm)[i];
    float4 d = reinterpret_cast<const float4*>(D)[i];
    float4 m = reinterpret_cast<const float4*>(mask)[i];
    uint32_t* o = g_bm + 4 * (size_t)i;
    __half2 h0 = __floats2half2_rn(a.x - g * d.x, m.x);
    __half2 h1 = __floats2half2_rn(a.y - g * d.y, m.y);
    __half2 h2 = __floats2half2_rn(a.z - g * d.z, m.z);
    __half2 h3 = __floats2half2_rn(a.w - g * d.w, m.w);
    o[0] = *reinterpret_cast<uint32_t*>(&h0);
    o[1] = *reinterpret_cast<uint32_t*>(&h1);
    o[2] = *reinterpret_cast<uint32_t*>(&h2);
    o[3] = *reinterpret_cast<uint32_t*>(&h3);
}

// ---------------------------------------------------------------------------
// LayerNorm: fp32 in -> fp16 out
// ---------------------------------------------------------------------------
__global__ void ln_kernel(const float* __restrict__ X,
                          const float* __restrict__ g,
                          const float* __restrict__ b,
                          __half* __restrict__ Y)
{
    const int row = blockIdx.x;
    const int tid = threadIdx.x;
    const float4* x4 = reinterpret_cast<const float4*>(X + (size_t)row * DM);
    float4 v = x4[tid];
    float s  = v.x + v.y + v.z + v.w;
    float ss = v.x*v.x + v.y*v.y + v.z*v.z + v.w*v.w;
    #pragma unroll
    for (int o = 16; o; o >>= 1) {
        s  += __shfl_xor_sync(0xffffffffu, s,  o);
        ss += __shfl_xor_sync(0xffffffffu, ss, o);
    }
    __shared__ float sh_s[4], sh_ss[4];
    if ((tid & 31) == 0) { sh_s[tid >> 5] = s; sh_ss[tid >> 5] = ss; }
    __syncthreads();
    s  = sh_s[0]  + sh_s[1]  + sh_s[2]  + sh_s[3];
    ss = sh_ss[0] + sh_ss[1] + sh_ss[2] + sh_ss[3];
    const float mu  = s * (1.0f / DM);
    const float var = ss * (1.0f / DM) - mu * mu;
    const float r   = rsqrtf(var + 1e-5f);
    const float4 gv = reinterpret_cast<const float4*>(g)[tid];
    const float4 bv = reinterpret_cast<const float4*>(b)[tid];
    __half2 h0 = __floats2half2_rn((v.x - mu) * r * gv.x + bv.x,
                                   (v.y - mu) * r * gv.y + bv.y);
    __half2 h1 = __floats2half2_rn((v.z - mu) * r * gv.z + bv.z,
                                   (v.w - mu) * r * gv.w + bv.w);
    __half2* y2 = reinterpret_cast<__half2*>(Y + (size_t)row * DM);
    y2[2 * tid]     = h0;
    y2[2 * tid + 1] = h1;
}

// ---------------------------------------------------------------------------
// Fused flash attention: no-max softmax, double-buffered K/V/BM, deferred l.
// ---------------------------------------------------------------------------
#define LDW  36
#define LBM  68
#define QS_OFF  0
#define KS_OFF  2304
#define VT_OFF  6912
#define BM_OFF  11520
#define PS_OFF  20224
#define RED_OFF 22528
#define SMATT_W 22784
__global__ void __launch_bounds__(256, 2)
attn_kernel(__half* __restrict__ attn)
{
    extern __shared__ uint32_t sw[];
    uint32_t* Ps = sw + PS_OFF;
    float* reds = reinterpret_cast<float*>(sw + RED_OFF);

    const int tid = threadIdx.x, lane = tid & 31, wid = tid >> 5;
    const int g = lane >> 2, t = lane & 3;
    const int lrow = lane & 7, quad = lane >> 3;
    const int wrow = (wid >> 2) * 32;
    const int wcol = (wid & 3) * 16;
    const int bh = blockIdx.y, b = bh >> 3, h = bh & 7;
    const int q0 = blockIdx.x * 64;

    const __half* qg = g_hq + ((size_t)bh * N_ + q0) * DH_;
    const __half* kg = g_hk + (size_t)bh * N_ * DH_;
    const __half* vg = g_hvT + (size_t)bh * DH_ * N_;
    const uint32_t* bmg = g_bm + ((size_t)b * N_ + q0) * N_;

    const uint32_t swb = smem_u32(sw);
    const uint32_t a_pat = (uint32_t)(((quad & 1) * 8 + lrow) * LDW + (quad >> 1) * 4);
    const uint32_t b_pat = (uint32_t)(((quad >> 1) * 8 + lrow) * LDW + (quad & 1) * 4);

    auto load_kvbm = [&](int it) {
        const int buf = it & 1;
        const uint32_t ks_a = swb + (KS_OFF + buf * 2304) * 4u;
        const uint32_t vt_a = swb + (VT_OFF + buf * 2304) * 4u;
        const uint32_t bm_a = swb + (BM_OFF + buf * 4352) * 4u;
        #pragma unroll
        for (int i = tid; i < 64 * 8; i += 256) {
            const int r = i >> 3, q = i & 7;
            CP_ASYNC16(ks_a + (uint32_t)(r * LDW + q * 4) * 4u,
                       kg + (size_t)(it * 64 + r) * DH_ + q * 8);
        }
        #pragma unroll
        for (int i = tid; i < 64 * 8; i += 256) {
            const int r = i >> 3, q = i & 7;
            CP_ASYNC16(vt_a + (uint32_t)(r * LDW + q * 4) * 4u,
                       vg + (size_t)r * N_ + it * 64 + q * 8);
        }
        #pragma unroll
        for (int i = tid; i < 64 * 16; i += 256) {
            const int r = i >> 4, q = i & 15;
            CP_ASYNC16(bm_a + (uint32_t)(r * LBM + q * 4) * 4u,
                       bmg + (size_t)r * N_ + it * 64 + q * 4);
        }
        CP_COMMIT();
    };

    #pragma unroll
    for (int i = tid; i < 64 * 8; i += 256) {
        const int r = i >> 3, q = i & 7;
        CP_ASYNC16(swb + (QS_OFF + r * LDW + q * 4) * 4u, qg + (size_t)r * DH_ + q * 8);
    }
    load_kvbm(0);

    float l_run[2][2] = {{0.f, 0.f}, {0.f, 0.f}};
    float o[2][2][4];
    #pragma unroll
    for (int mt = 0; mt < 2; mt++)
        #pragma unroll
        for (int nt = 0; nt < 2; nt++)
            #pragma unroll
            for (int r = 0; r < 4; r++) o[mt][nt][r] = 0.f;

    const float LN16 = 2.772588722f;

    for (int it = 0; it < 16; it++) {
        cp_wait<0>();
        __syncthreads();
        if (it + 1 < 16) load_kvbm(it + 1);

        const int buf = it & 1;
        const uint32_t qs_a = swb;
        const uint32_t ks_a = swb + (KS_OFF + buf * 2304) * 4u;
        const uint32_t vt_a = swb + (VT_OFF + buf * 2304) * 4u;
        const uint32_t* bms = sw + BM_OFF + buf * 4352;

        float s[2][2][4];
        #pragma unroll
        for (int mt = 0; mt < 2; mt++)
            #pragma unroll
            for (int nt = 0; nt < 2; nt++)
                #pragma unroll
                for (int r = 0; r < 4; r++) s[mt][nt][r] = 0.f;
        #pragma unroll
        for (int kk = 0; kk < 4; kk++) {
            const int kb = kk * 8;
            uint32_t qa[2][4], kf[2][2];
            #pragma unroll
            for (int mt = 0; mt < 2; mt++)
                LDSM_X4(qa[mt][0], qa[mt][1], qa[mt][2], qa[mt][3],
                        qs_a + (uint32_t)((wrow + mt * 16) * LDW + kb + a_pat) * 4u);
            LDSM_X4(kf[0][0], kf[0][1], kf[1][0], kf[1][1],
                    ks_a + (uint32_t)(wcol * LDW + kb + b_pat) * 4u);
            #pragma unroll
            for (int mt = 0; mt < 2; mt++)
                #pragma unroll
                for (int nt = 0; nt < 2; nt++)
                    mma_f16(s[mt][nt][0], s[mt][nt][1], s[mt][nt][2], s[mt][nt][3],
                            qa[mt][0], qa[mt][1], qa[mt][2], qa[mt][3],
                            kf[nt][0], kf[nt][1]);
        }

        #pragma unroll
        for (int mt = 0; mt < 2; mt++)
            #pragma unroll
            for (int hf = 0; hf < 2; hf++)
                #pragma unroll
                for (int nt = 0; nt < 2; nt++) {
                    const int rl = wrow + mt * 16 + hf * 8 + g;
                    const int cl = wcol + nt * 8 + 2 * t;
                    uint2 w = *reinterpret_cast<const uint2*>(bms + rl * LBM + cl);
                    __half2 h0 = *reinterpret_cast<__half2*>(&w.x);
                    __half2 h1 = *reinterpret_cast<__half2*>(&w.y);
                    float x0 = fmaf(s[mt][nt][hf * 2 + 0], 0.125f,
                                    __half2float(__low2half(h0)));
                    float x1 = fmaf(s[mt][nt][hf * 2 + 1], 0.125f,
                                    __half2float(__low2half(h1)));
                    float e0 = __expf(x0 - LN16);
                    float e1 = __expf(x1 - LN16);
                    l_run[mt][hf] += e0 + e1;
                    __half2 ev = __floats2half2_rn(e0, e1);
                    __half2 mm = __halves2half2(__high2half(h0), __high2half(h1));
                    __half2 pv = __hmul2(ev, mm);
                    Ps[rl * LDW + wcol / 2 + nt * 4 + t] =
                        *reinterpret_cast<uint32_t*>(&pv);
                }
        __syncthreads();

        const uint32_t ps_a = swb + PS_OFF * 4u;
        #pragma unroll
        for (int kk = 0; kk < 4; kk++) {
            const int kb = kk * 8;
            uint32_t pa[2][4], vb[2][2];
            #pragma unroll
            for (int mt = 0; mt < 2; mt++)
                LDSM_X4(pa[mt][0], pa[mt][1], pa[mt][2], pa[mt][3],
                        ps_a + (uint32_t)((wrow + mt * 16) * LDW + kb + a_pat) * 4u);
            LDSM_X4(vb[0][0], vb[0][1], vb[1][0], vb[1][1],
                    vt_a + (uint32_t)(wcol * LDW + kb + b_pat) * 4u);
            #pragma unroll
            for (int mt = 0; mt < 2; mt++)
                #pragma unroll
                for (int nt = 0; nt < 2; nt++)
                    mma_f16(o[mt][nt][0], o[mt][nt][1], o[mt][nt][2], o[mt][nt][3],
                            pa[mt][0], pa[mt][1], pa[mt][2], pa[mt][3],
                            vb[nt][0], vb[nt][1]);
        }
    }

    #pragma unroll
    for (int x = 1; x <= 2; x <<= 1)
        #pragma unroll
        for (int mt = 0; mt < 2; mt++)
            #pragma unroll
            for (int hf = 0; hf < 2; hf++)
                l_run[mt][hf] += __shfl_xor_sync(0xffffffffu, l_run[mt][hf], x);
    __syncthreads();
    if (t == 0) {
        #pragma unroll
        for (int mt = 0; mt < 2; mt++)
            #pragma unroll
            for (int hf = 0; hf < 2; hf++)
                reds[(wid & 3) * 64 + wrow + mt * 16 + hf * 8 + g] = l_run[mt][hf];
    }
    __syncthreads();

    #pragma unroll
    for (int mt = 0; mt < 2; mt++)
        #pragma unroll
        for (int hf = 0; hf < 2; hf++) {
            const int r = wrow + mt * 16 + hf * 8 + g;
            const float l_tot = reds[r] + reds[64 + r] + reds[128 + r] + reds[192 + r];
            const float inv = 1.0f / l_tot;
            const int row = q0 + r;
            __half* dst = attn + ((size_t)b * N_ + row) * DM + h * DH_;
            #pragma unroll
            for (int nt = 0; nt < 2; nt++) {
                const int d = wcol + nt * 8 + 2 * t;
                float v0 = o[mt][nt][hf * 2 + 0] * inv;
                float v1 = o[mt][nt][hf * 2 + 1] * inv;
                v0 = v0 > 0.f ? v0 : 0.01f * v0;
                v1 = v1 > 0.f ? v1 : 0.01f * v1;
                __half2 hv = __floats2half2_rn(v0, v1);
                *reinterpret_cast<__half2*>(dst + d) = hv;
            }
        }
}

// ---------------------------------------------------------------------------
// fp16 mma GEMM (BN=64): BM=128, BK=64, 4 warps, warp tile 64x32, 2-stage.
// ---------------------------------------------------------------------------
template<int EPI>
__global__ void __launch_bounds__(128, 4)
tc_gemm(const __half* __restrict__ A, const __half* __restrict__ Bw,
        const float* __restrict__ bias, void* __restrict__ Cv,
        int M, int N, int K,
        const float* __restrict__ e1)
{
    constexpr int THREADS = 128;
    constexpr int STG = (128 + 64) * LDW;

    extern __shared__ uint32_t sw[];

    const int tid  = threadIdx.x;
    const int wid  = tid >> 5;
    const int lane = tid & 31;
    const int g    = lane >> 2;
    const int t    = lane & 3;
    const int lrow = lane & 7, quad = lane >> 3;
    const int wr   = (wid >> 1) * 64;
    const int wc   = (wid & 1) * 32;

    const int brow = blockIdx.y * 128;
    const int bcol = blockIdx.x * 64;
    const __half* Ab = A  + (size_t)brow * K;
    const __half* Bb = Bw + (size_t)bcol * K;

    float c[4][4][4];
    #pragma unroll
    for (int i = 0; i < 4; i++)
        #pragma unroll
        for (int j = 0; j < 4; j++)
            #pragma unroll
            for (int r = 0; r < 4; r++) c[i][j][r] = 0.0f;

    const uint32_t smb = smem_u32(sw);
    const uint32_t a_pat = (uint32_t)(((quad & 1) * 8 + lrow) * LDW + (quad >> 1) * 4);
    const uint32_t b_pat = (uint32_t)(((quad >> 1) * 8 + lrow) * LDW + (quad & 1) * 4);

    auto load_stage = [&](int s) {
        const int buf = s & 1;
        const uint32_t as = smb + (uint32_t)(buf * STG) * 4u;
        const uint32_t bs = as + 128u * LDW * 4u;
        const __half* ag = Ab + s * 64;
        #pragma unroll
        for (int i = tid; i < 128 * 8; i += THREADS) {
            const int r = i >> 3, q = i & 7;
            CP_ASYNC16(as + (uint32_t)(r * LDW + q * 4) * 4u,
                       ag + (size_t)r * K + q * 8);
        }
        const __half* bg = Bb + s * 64;
        #pragma unroll
        for (int i = tid; i < 64 * 8; i += THREADS) {
            const int r = i >> 3, q = i & 7;
            CP_ASYNC16(bs + (uint32_t)(r * LDW + q * 4) * 4u,
                       bg + (size_t)r * K + q * 8);
        }
        CP_COMMIT();
    };

    const int S = K / 64;
    load_stage(0);

    for (int s = 0; s < S; s++) {
        if (s + 1 < S) { load_stage(s + 1); cp_wait<1>(); }
        else           { cp_wait<0>(); }
        __syncthreads();

        const int buf = s & 1;
        const uint32_t abase = smb + (uint32_t)(buf * STG) * 4u;
        const uint32_t bbase = abase + 128u * LDW * 4u;

        #pragma unroll
        for (int ks = 0; ks < 4; ks++) {
            const int kb = ks * 8;
            uint32_t af[4][4];
            #pragma unroll
            for (int mt = 0; mt < 4; mt++)
                LDSM_X4(af[mt][0], af[mt][1], af[mt][2], af[mt][3],
                        abase + (uint32_t)((wr + mt * 16) * LDW + kb + a_pat) * 4u);
            uint32_t bf[4][2];
            #pragma unroll
            for (int np = 0; np < 2; np++)
                LDSM_X4(bf[2 * np][0], bf[2 * np][1], bf[2 * np + 1][0], bf[2 * np + 1][1],
                        bbase + (uint32_t)((wc + np * 16) * LDW + kb + b_pat) * 4u);
            #pragma unroll
            for (int mt = 0; mt < 4; mt++)
                #pragma unroll
                for (int nt = 0; nt < 4; nt++)
                    mma_f16(c[mt][nt][0], c[mt][nt][1], c[mt][nt][2], c[mt][nt][3],
                            af[mt][0], af[mt][1], af[mt][2], af[mt][3],
                            bf[nt][0], bf[nt][1]);
        }
        __syncthreads();
    }

    #pragma unroll
    for (int mt = 0; mt < 4; mt++) {
        #pragma unroll
        for (int half = 0; half < 2; half++) {
            const int row = brow + wr + mt * 16 + g + half * 8;
            #pragma unroll
            for (int nt = 0; nt < 4; nt++) {
                const int col = bcol + wc + nt * 8 + 2 * t;
                float v0 = c[mt][nt][half * 2 + 0];
                float v1 = c[mt][nt][half * 2 + 1];
                if constexpr (EPI == 4) {
                    float* C = (float*)Cv;
                    if (bias) { v0 += bias[col]; v1 += bias[col + 1]; }
                    float2 r2 = *reinterpret_cast<const float2*>(e1 + (size_t)row * N + col);
                    *reinterpret_cast<float2*>(C + (size_t)row * N + col) =
                        make_float2(v0 + r2.x, v1 + r2.y);
                } else {  // EPI 5
                    __half* C = (__half*)Cv;
                    v0 += bias[col]; v1 += bias[col + 1];
                    *reinterpret_cast<__half2*>(C + (size_t)row * N + col) =
                        __floats2half2_rn(fmaxf(v0, 0.f), fmaxf(v1, 0.f));
                }
            }
        }
    }
}

// ---------------------------------------------------------------------------
// Wide fp16 mma GEMM (BN=128): BM=128, BK=64, 4 warps, warp tile 64x64 (2x2),
// 2-stage. High MMA ILP (32 MMAs per ks-step). For grid-rich GEMMs.
//   EPI 1: QKV scatter (+bias)   EPI 5: +bias, relu -> fp16
// ---------------------------------------------------------------------------
template<int EPI>
__global__ void __launch_bounds__(128, 2)
tc_gemm_w(const __half* __restrict__ A, const __half* __restrict__ Bw,
          const float* __restrict__ bias, void* __restrict__ Cv,
          int M, int N, int K)
{
    constexpr int THREADS = 128;
    constexpr int STG = (128 + 128) * LDW;

    extern __shared__ uint32_t sw[];

    const int tid  = threadIdx.x;
    const int wid  = tid >> 5;
    const int lane = tid & 31;
    const int g    = lane >> 2;
    const int t    = lane & 3;
    const int lrow = lane & 7, quad = lane >> 3;
    const int wr   = (wid >> 1) * 64;
    const int wc   = (wid & 1) * 64;

    const int brow = blockIdx.y * 128;
    const int bcol = blockIdx.x * 128;
    const __half* Ab = A  + (size_t)brow * K;
    const __half* Bb = Bw + (size_t)bcol * K;

    float c[4][8][4];
    #pragma unroll
    for (int i = 0; i < 4; i++)
        #pragma unroll
        for (int j = 0; j < 8; j++)
            #pragma unroll
            for (int r = 0; r < 4; r++) c[i][j][r] = 0.0f;

    const uint32_t smb = smem_u32(sw);
    const uint32_t a_pat = (uint32_t)(((quad & 1) * 8 + lrow) * LDW + (quad >> 1) * 4);
    const uint32_t b_pat = (uint32_t)(((quad >> 1) * 8 + lrow) * LDW + (quad & 1) * 4);

    auto load_stage = [&](int s) {
        const int buf = s & 1;
        const uint32_t as = smb + (uint32_t)(buf * STG) * 4u;
        const uint32_t bs = as + 128u * LDW * 4u;
        const __half* ag = Ab + s * 64;
        #pragma unroll
        for (int i = tid; i < 128 * 8; i += THREADS) {
            const int r = i >> 3, q = i & 7;
            CP_ASYNC16(as + (uint32_t)(r * LDW + q * 4) * 4u,
                       ag + (size_t)r * K + q * 8);
        }
        const __half* bg = Bb + s * 64;
        #pragma unroll
        for (int i = tid; i < 128 * 8; i += THREADS) {
            const int r = i >> 3, q = i & 7;
            CP_ASYNC16(bs + (uint32_t)(r * LDW + q * 4) * 4u,
                       bg + (size_t)r * K + q * 8);
        }
        CP_COMMIT();
    };

    const int S = K / 64;
    load_stage(0);

    for (int s = 0; s < S; s++) {
        if (s + 1 < S) { load_stage(s + 1); cp_wait<1>(); }
        else           { cp_wait<0>(); }
        __syncthreads();

        const int buf = s & 1;
        const uint32_t abase = smb + (uint32_t)(buf * STG) * 4u;
        const uint32_t bbase = abase + 128u * LDW * 4u;

        #pragma unroll
        for (int ks = 0; ks < 4; ks++) {
            const int kb = ks * 8;
            uint32_t af[4][4];
            #pragma unroll
            for (int mt = 0; mt < 4; mt++)
                LDSM_X4(af[mt][0], af[mt][1], af[mt][2], af[mt][3],
                        abase + (uint32_t)((wr + mt * 16) * LDW + kb + a_pat) * 4u);
            uint32_t bf[8][2];
            #pragma unroll
            for (int np = 0; np < 4; np++)
                LDSM_X4(bf[2 * np][0], bf[2 * np][1], bf[2 * np + 1][0], bf[2 * np + 1][1],
                        bbase + (uint32_t)((wc + np * 16) * LDW + kb + b_pat) * 4u);
            #pragma unroll
            for (int mt = 0; mt < 4; mt++)
                #pragma unroll
                for (int nt = 0; nt < 8; nt++)
                    mma_f16(c[mt][nt][0], c[mt][nt][1], c[mt][nt][2], c[mt][nt][3],
                            af[mt][0], af[mt][1], af[mt][2], af[mt][3],
                            bf[nt][0], bf[nt][1]);
        }
        __syncthreads();
    }

    #pragma unroll
    for (int mt = 0; mt < 4; mt++) {
        #pragma unroll
        for (int half = 0; half < 2; half++) {
            const int row = brow + wr + mt * 16 + g + half * 8;
            #pragma unroll
            for (int nt = 0; nt < 8; nt++) {
                const int col = bcol + wc + nt * 8 + 2 * t;
                float v0 = c[mt][nt][half * 2 + 0];
                float v1 = c[mt][nt][half * 2 + 1];
                if constexpr (EPI == 1) {
                    v0 += bias[col]; v1 += bias[col + 1];
                    const int h  = col / (3 * DH_);
                    const int cc = col % (3 * DH_);
                    const int bb = row >> 10;
                    const int n  = row & (N_ - 1);
                    if (cc < DH_) {
                        __half* base = g_hvT + ((size_t)(bb * H_ + h) * DH_ + cc) * N_ + n;
                        base[0]  = __float2half(v0);
                        base[N_] = __float2half(v1);
                    } else if (cc < 2 * DH_) {
                        *reinterpret_cast<__half2*>(
                            g_hq + ((size_t)(bb * H_ + h) * N_ + n) * DH_ + (cc - DH_)) =
                            __floats2half2_rn(v0, v1);
                    } else {
                        *reinterpret_cast<__half2*>(
                            g_hk + ((size_t)(bb * H_ + h) * N_ + n) * DH_ + (cc - 2 * DH_)) =
                            __floats2half2_rn(v0, v1);
                    }
                } else {  // EPI 5
                    __half* C = (__half*)Cv;
                    v0 += bias[col]; v1 += bias[col + 1];
                    *reinterpret_cast<__half2*>(C + (size_t)row * N + col) =
                        __floats2half2_rn(fmaxf(v0, 0.f), fmaxf(v1, 0.f));
                }
            }
        }
    }
}

// ---------------------------------------------------------------------------
// Launch
// ---------------------------------------------------------------------------
extern "C" void kernel_launch(void* const* d_in, const int* in_sizes, int n_in,
                              void* d_out, int out_size)
{
    const float* Z        = (const float*)d_in[0];
    const float* Dm       = (const float*)d_in[1];
    const float* new_mask = (const float*)d_in[2];
    const float* mask     = (const float*)d_in[3];
    const float* Wqkv     = (const float*)d_in[4];
    const float* bqkv     = (const float*)d_in[5];
    const float* Wo       = (const float*)d_in[6];
    const float* g1       = (const float*)d_in[7];
    const float* b1       = (const float*)d_in[8];
    const float* g2       = (const float*)d_in[9];
    const float* b2       = (const float*)d_in[10];
    const float* Wp1      = (const float*)d_in[11];
    const float* bp1      = (const float*)d_in[12];
    const float* Wp2      = (const float*)d_in[13];
    const float* bp2      = (const float*)d_in[14];
    const float* gamma    = (const float*)d_in[15];
    float* out = (float*)d_out;

    __half *pZnh, *pattnh, *pZn2h, *pHidh, *phWqkv, *phWo, *phWp1, *phWp2;
    float *pZ2;
    cudaGetSymbolAddress((void**)&pZnh,   g_Znh);
    cudaGetSymbolAddress((void**)&pattnh, g_attnh);
    cudaGetSymbolAddress((void**)&pZ2,    g_Z2);
    cudaGetSymbolAddress((void**)&pZn2h,  g_Zn2h);
    cudaGetSymbolAddress((void**)&pHidh,  g_Hidh);
    cudaGetSymbolAddress((void**)&phWqkv, g_hWqkv);
    cudaGetSymbolAddress((void**)&phWo,   g_hWo);
    cudaGetSymbolAddress((void**)&phWp1,  g_hWp1);
    cudaGetSymbolAddress((void**)&phWp2,  g_hWp2);

    const int SMG   = 2 * (128 + 64) * LDW * 4;    // 55296
    const int SMGW  = 2 * (128 + 128) * LDW * 4;   // 73728
    const int SMATT = SMATT_W * 4;                 // 91136
    cudaFuncSetAttribute(tc_gemm_w<1>, cudaFuncAttributeMaxDynamicSharedMemorySize, SMGW);
    cudaFuncSetAttribute(tc_gemm_w<5>, cudaFuncAttributeMaxDynamicSharedMemorySize, SMGW);
    cudaFuncSetAttribute(tc_gemm<4>, cudaFuncAttributeMaxDynamicSharedMemorySize, SMG);
    cudaFuncSetAttribute(attn_kernel, cudaFuncAttributeMaxDynamicSharedMemorySize, SMATT);

    const int NW4 = Q0 + Q1 + Q2 + Q3;

    // 0) weights -> fp16; packed bias/mask precompute
    f2h_all<<<(NW4 + 255)/256, 256>>>(Wqkv, Wo, Wp1, Wp2);
    bm_kernel<<<(B_*N_*N_/4)/256, 256>>>(new_mask, Dm, mask, gamma);

    // 1) LN1 -> fp16
    ln_kernel<<<MROWS, 128>>>(Z, g1, b1, pZnh);

    // 2) QKV -> fp16 q/k/vT (wide tile: 12x32 = 384 CTAs)
    tc_gemm_w<1><<<dim3(QKV3/128, MROWS/128), 128, SMGW>>>(
        pZnh, phWqkv, bqkv, nullptr, MROWS, QKV3, DM);

    // 3) Flash attention -> fp16 attn
    attn_kernel<<<dim3(N_/64, B_*H_), 256, SMATT>>>(pattnh);

    // 4) Wo + residual -> fp32 Z2 (BN=64: 256 CTAs)
    tc_gemm<4><<<dim3(DM/64, MROWS/128), 128, SMG>>>(
        pattnh, phWo, nullptr, pZ2, MROWS, DM, DM, Z);

    // 5) LN2 -> fp16
    ln_kernel<<<MROWS, 128>>>(pZ2, g2, b2, pZn2h);

    // 6) MLP1 + relu -> fp16 Hid (wide tile: 16x32 = 512 CTAs)
    tc_gemm_w<5><<<dim3(DI/128, MROWS/128), 128, SMGW>>>(
        pZn2h, phWp1, bp1, pHidh, MROWS, DI, DM);

    // 7) MLP2 + bias + residual -> fp32 out (BN=64: 256 CTAs)
    tc_gemm<4><<<dim3(DM/64, MROWS/128), 128, SMG>>>(
        pHidh, phWp2, bp2, out, MROWS, DM, DI, pZ2);
}

// round 15
// speedup vs baseline: 1.1046x; 1.1046x over previous
#include <cuda_runtime.h>
#include <cuda_fp16.h>
#include <cstdint>
#include <math.h>

#define B_   4
#define N_   1024
#define DM   512
#define H_   8
#define DH_  64
#define DI   2048
#define MROWS (B_*N_)          // 4096
#define QKV3 (3*DM)            // 1536

// ---------------------------------------------------------------------------
// Scratch (device globals)
// ---------------------------------------------------------------------------
__device__ __half g_Znh [MROWS*DM];
__device__ __half g_hq  [B_*H_*N_*DH_];
__device__ __half g_hk  [B_*H_*N_*DH_];
__device__ __half g_hvT [B_*H_*DH_*N_];
__device__ __half g_attnh[MROWS*DM];
__device__ float  g_Z2  [MROWS*DM];
__device__ __half g_Zn2h[MROWS*DM];
__device__ __half g_Hidh[MROWS*DI];
__device__ __half g_hWqkv[QKV3*DM];
__device__ __half g_hWo [DM*DM];
__device__ __half g_hWp1[DI*DM];
__device__ __half g_hWp2[DM*DI];
__device__ uint32_t g_bm[(size_t)B_*N_*N_];   // packed half2(nm - gamma*D, mask)

// ---------------------------------------------------------------------------
// Helpers
// ---------------------------------------------------------------------------
__device__ __forceinline__ uint32_t smem_u32(const void* p) {
    uint32_t a;
    asm("{ .reg .u64 t; cvta.to.shared.u64 t, %1; cvt.u32.u64 %0, t; }" : "=r"(a) : "l"(p));
    return a;
}
#define CP_ASYNC16(sa, ga) \
    asm volatile("cp.async.cg.shared.global [%0], [%1], 16;" :: "r"(sa), "l"(ga))
#define CP_COMMIT() asm volatile("cp.async.commit_group;" ::: "memory")
template<int Nw> __device__ __forceinline__ void cp_wait() {
    asm volatile("cp.async.wait_group %0;" :: "n"(Nw) : "memory");
}
#define LDSM_X4(r0, r1, r2, r3, addr) \
    asm volatile("ldmatrix.sync.aligned.m8n8.x4.shared.b16 {%0,%1,%2,%3}, [%4];" \
        : "=r"(r0), "=r"(r1), "=r"(r2), "=r"(r3) : "r"(addr))
__device__ __forceinline__ void mma_f16(float& c0, float& c1, float& c2, float& c3,
                                        uint32_t a0, uint32_t a1, uint32_t a2, uint32_t a3,
                                        uint32_t b0, uint32_t b1) {
    asm volatile(
        "mma.sync.aligned.m16n8k16.row.col.f32.f16.f16.f32 "
        "{%0,%1,%2,%3},{%4,%5,%6,%7},{%8,%9},{%0,%1,%2,%3};"
        : "+f"(c0), "+f"(c1), "+f"(c2), "+f"(c3)
        : "r"(a0), "r"(a1), "r"(a2), "r"(a3), "r"(b0), "r"(b1));
}

// ---------------------------------------------------------------------------
// Fused prep: fp32->fp16 weights + packed bias/mask, one launch.
// ---------------------------------------------------------------------------
#define Q0 (QKV3*DM/4)
#define Q1 (DM*DM/4)
#define Q2 (DI*DM/4)
#define Q3 (DM*DI/4)
#define NW4 (Q0+Q1+Q2+Q3)
#define NBM4 ((B_*N_*N_)/4)
__global__ void prep_all(const float* __restrict__ w0, const float* __restrict__ w1,
                         const float* __restrict__ w2, const float* __restrict__ w3,
                         const float* __restrict__ nm, const float* __restrict__ D,
                         const float* __restrict__ mask, const float* __restrict__ gptr)
{
    int i = blockIdx.x * 256 + threadIdx.x;
    if (i < NW4) {
        const float* s; __half* d;
        if (i < Q0)                { s = w0; d = g_hWqkv; }
        else if ((i -= Q0) < Q1)   { s = w1; d = g_hWo; }
        else if ((i -= Q1) < Q2)   { s = w2; d = g_hWp1; }
        else           { i -= Q2;    s = w3; d = g_hWp2; }
        float4 v = reinterpret_cast<const float4*>(s)[i];
        reinterpret_cast<__half2*>(d)[2 * i]     = __floats2half2_rn(v.x, v.y);
        reinterpret_cast<__half2*>(d)[2 * i + 1] = __floats2half2_rn(v.z, v.w);
        return;
    }
    i -= NW4;
    if (i >= NBM4) return;
    const float g = gptr[0];
    float4 a = reinterpret_cast<const float4*>(nm)[i];
    float4 d4 = reinterpret_cast<const float4*>(D)[i];
    float4 m = reinterpret_cast<const float4*>(mask)[i];
    uint32_t* o = g_bm + 4 * (size_t)i;
    __half2 h0 = __floats2half2_rn(a.x - g * d4.x, m.x);
    __half2 h1 = __floats2half2_rn(a.y - g * d4.y, m.y);
    __half2 h2 = __floats2half2_rn(a.z - g * d4.z, m.z);
    __half2 h3 = __floats2half2_rn(a.w - g * d4.w, m.w);
    o[0] = *reinterpret_cast<uint32_t*>(&h0);
    o[1] = *reinterpret_cast<uint32_t*>(&h1);
    o[2] = *reinterpret_cast<uint32_t*>(&h2);
    o[3] = *reinterpret_cast<uint32_t*>(&h3);
}

// ---------------------------------------------------------------------------
// LayerNorm: fp32 in -> fp16 out
// ---------------------------------------------------------------------------
__global__ void ln_kernel(const float* __restrict__ X,
                          const float* __restrict__ g,
                          const float* __restrict__ b,
                          __half* __restrict__ Y)
{
    const int row = blockIdx.x;
    const int tid = threadIdx.x;
    const float4* x4 = reinterpret_cast<const float4*>(X + (size_t)row * DM);
    float4 v = x4[tid];
    float s  = v.x + v.y + v.z + v.w;
    float ss = v.x*v.x + v.y*v.y + v.z*v.z + v.w*v.w;
    #pragma unroll
    for (int o = 16; o; o >>= 1) {
        s  += __shfl_xor_sync(0xffffffffu, s,  o);
        ss += __shfl_xor_sync(0xffffffffu, ss, o);
    }
    __shared__ float sh_s[4], sh_ss[4];
    if ((tid & 31) == 0) { sh_s[tid >> 5] = s; sh_ss[tid >> 5] = ss; }
    __syncthreads();
    s  = sh_s[0]  + sh_s[1]  + sh_s[2]  + sh_s[3];
    ss = sh_ss[0] + sh_ss[1] + sh_ss[2] + sh_ss[3];
    const float mu  = s * (1.0f / DM);
    const float var = ss * (1.0f / DM) - mu * mu;
    const float r   = rsqrtf(var + 1e-5f);
    const float4 gv = reinterpret_cast<const float4*>(g)[tid];
    const float4 bv = reinterpret_cast<const float4*>(b)[tid];
    __half2 h0 = __floats2half2_rn((v.x - mu) * r * gv.x + bv.x,
                                   (v.y - mu) * r * gv.y + bv.y);
    __half2 h1 = __floats2half2_rn((v.z - mu) * r * gv.z + bv.z,
                                   (v.w - mu) * r * gv.w + bv.w);
    __half2* y2 = reinterpret_cast<__half2*>(Y + (size_t)row * DM);
    y2[2 * tid]     = h0;
    y2[2 * tid + 1] = h1;
}

// ---------------------------------------------------------------------------
// Fused flash attention: no-max softmax, double-buffered K/V/BM, deferred l.
// ---------------------------------------------------------------------------
#define LDW  36
#define LBM  68
#define QS_OFF  0
#define KS_OFF  2304
#define VT_OFF  6912
#define BM_OFF  11520
#define PS_OFF  20224
#define RED_OFF 22528
#define SMATT_W 22784
__global__ void __launch_bounds__(256, 2)
attn_kernel(__half* __restrict__ attn)
{
    extern __shared__ uint32_t sw[];
    uint32_t* Ps = sw + PS_OFF;
    float* reds = reinterpret_cast<float*>(sw + RED_OFF);

    const int tid = threadIdx.x, lane = tid & 31, wid = tid >> 5;
    const int g = lane >> 2, t = lane & 3;
    const int lrow = lane & 7, quad = lane >> 3;
    const int wrow = (wid >> 2) * 32;
    const int wcol = (wid & 3) * 16;
    const int bh = blockIdx.y, b = bh >> 3, h = bh & 7;
    const int q0 = blockIdx.x * 64;

    const __half* qg = g_hq + ((size_t)bh * N_ + q0) * DH_;
    const __half* kg = g_hk + (size_t)bh * N_ * DH_;
    const __half* vg = g_hvT + (size_t)bh * DH_ * N_;
    const uint32_t* bmg = g_bm + ((size_t)b * N_ + q0) * N_;

    const uint32_t swb = smem_u32(sw);
    const uint32_t a_pat = (uint32_t)(((quad & 1) * 8 + lrow) * LDW + (quad >> 1) * 4);
    const uint32_t b_pat = (uint32_t)(((quad >> 1) * 8 + lrow) * LDW + (quad & 1) * 4);

    auto load_kvbm = [&](int it) {
        const int buf = it & 1;
        const uint32_t ks_a = swb + (KS_OFF + buf * 2304) * 4u;
        const uint32_t vt_a = swb + (VT_OFF + buf * 2304) * 4u;
        const uint32_t bm_a = swb + (BM_OFF + buf * 4352) * 4u;
        #pragma unroll
        for (int i = tid; i < 64 * 8; i += 256) {
            const int r = i >> 3, q = i & 7;
            CP_ASYNC16(ks_a + (uint32_t)(r * LDW + q * 4) * 4u,
                       kg + (size_t)(it * 64 + r) * DH_ + q * 8);
        }
        #pragma unroll
        for (int i = tid; i < 64 * 8; i += 256) {
            const int r = i >> 3, q = i & 7;
            CP_ASYNC16(vt_a + (uint32_t)(r * LDW + q * 4) * 4u,
                       vg + (size_t)r * N_ + it * 64 + q * 8);
        }
        #pragma unroll
        for (int i = tid; i < 64 * 16; i += 256) {
            const int r = i >> 4, q = i & 15;
            CP_ASYNC16(bm_a + (uint32_t)(r * LBM + q * 4) * 4u,
                       bmg + (size_t)r * N_ + it * 64 + q * 4);
        }
        CP_COMMIT();
    };

    #pragma unroll
    for (int i = tid; i < 64 * 8; i += 256) {
        const int r = i >> 3, q = i & 7;
        CP_ASYNC16(swb + (QS_OFF + r * LDW + q * 4) * 4u, qg + (size_t)r * DH_ + q * 8);
    }
    load_kvbm(0);

    float l_run[2][2] = {{0.f, 0.f}, {0.f, 0.f}};
    float o[2][2][4];
    #pragma unroll
    for (int mt = 0; mt < 2; mt++)
        #pragma unroll
        for (int nt = 0; nt < 2; nt++)
            #pragma unroll
            for (int r = 0; r < 4; r++) o[mt][nt][r] = 0.f;

    const float LN16 = 2.772588722f;

    for (int it = 0; it < 16; it++) {
        cp_wait<0>();
        __syncthreads();
        if (it + 1 < 16) load_kvbm(it + 1);

        const int buf = it & 1;
        const uint32_t qs_a = swb;
        const uint32_t ks_a = swb + (KS_OFF + buf * 2304) * 4u;
        const uint32_t vt_a = swb + (VT_OFF + buf * 2304) * 4u;
        const uint32_t* bms = sw + BM_OFF + buf * 4352;

        float s[2][2][4];
        #pragma unroll
        for (int mt = 0; mt < 2; mt++)
            #pragma unroll
            for (int nt = 0; nt < 2; nt++)
                #pragma unroll
                for (int r = 0; r < 4; r++) s[mt][nt][r] = 0.f;
        #pragma unroll
        for (int kk = 0; kk < 4; kk++) {
            const int kb = kk * 8;
            uint32_t qa[2][4], kf[2][2];
            #pragma unroll
            for (int mt = 0; mt < 2; mt++)
                LDSM_X4(qa[mt][0], qa[mt][1], qa[mt][2], qa[mt][3],
                        qs_a + (uint32_t)((wrow + mt * 16) * LDW + kb + a_pat) * 4u);
            LDSM_X4(kf[0][0], kf[0][1], kf[1][0], kf[1][1],
                    ks_a + (uint32_t)(wcol * LDW + kb + b_pat) * 4u);
            #pragma unroll
            for (int mt = 0; mt < 2; mt++)
                #pragma unroll
                for (int nt = 0; nt < 2; nt++)
                    mma_f16(s[mt][nt][0], s[mt][nt][1], s[mt][nt][2], s[mt][nt][3],
                            qa[mt][0], qa[mt][1], qa[mt][2], qa[mt][3],
                            kf[nt][0], kf[nt][1]);
        }

        #pragma unroll
        for (int mt = 0; mt < 2; mt++)
            #pragma unroll
            for (int hf = 0; hf < 2; hf++)
                #pragma unroll
                for (int nt = 0; nt < 2; nt++) {
                    const int rl = wrow + mt * 16 + hf * 8 + g;
                    const int cl = wcol + nt * 8 + 2 * t;
                    uint2 w = *reinterpret_cast<const uint2*>(bms + rl * LBM + cl);
                    __half2 h0 = *reinterpret_cast<__half2*>(&w.x);
                    __half2 h1 = *reinterpret_cast<__half2*>(&w.y);
                    float x0 = fmaf(s[mt][nt][hf * 2 + 0], 0.125f,
                                    __half2float(__low2half(h0)));
                    float x1 = fmaf(s[mt][nt][hf * 2 + 1], 0.125f,
                                    __half2float(__low2half(h1)));
                    float e0 = __expf(x0 - LN16);
                    float e1 = __expf(x1 - LN16);
                    l_run[mt][hf] += e0 + e1;
                    __half2 ev = __floats2half2_rn(e0, e1);
                    __half2 mm = __halves2half2(__high2half(h0), __high2half(h1));
                    __half2 pv = __hmul2(ev, mm);
                    Ps[rl * LDW + wcol / 2 + nt * 4 + t] =
                        *reinterpret_cast<uint32_t*>(&pv);
                }
        __syncthreads();

        const uint32_t ps_a = swb + PS_OFF * 4u;
        #pragma unroll
        for (int kk = 0; kk < 4; kk++) {
            const int kb = kk * 8;
            uint32_t pa[2][4], vb[2][2];
            #pragma unroll
            for (int mt = 0; mt < 2; mt++)
                LDSM_X4(pa[mt][0], pa[mt][1], pa[mt][2], pa[mt][3],
                        ps_a + (uint32_t)((wrow + mt * 16) * LDW + kb + a_pat) * 4u);
            LDSM_X4(vb[0][0], vb[0][1], vb[1][0], vb[1][1],
                    vt_a + (uint32_t)(wcol * LDW + kb + b_pat) * 4u);
            #pragma unroll
            for (int mt = 0; mt < 2; mt++)
                #pragma unroll
                for (int nt = 0; nt < 2; nt++)
                    mma_f16(o[mt][nt][0], o[mt][nt][1], o[mt][nt][2], o[mt][nt][3],
                            pa[mt][0], pa[mt][1], pa[mt][2], pa[mt][3],
                            vb[nt][0], vb[nt][1]);
        }
    }

    #pragma unroll
    for (int x = 1; x <= 2; x <<= 1)
        #pragma unroll
        for (int mt = 0; mt < 2; mt++)
            #pragma unroll
            for (int hf = 0; hf < 2; hf++)
                l_run[mt][hf] += __shfl_xor_sync(0xffffffffu, l_run[mt][hf], x);
    __syncthreads();
    if (t == 0) {
        #pragma unroll
        for (int mt = 0; mt < 2; mt++)
            #pragma unroll
            for (int hf = 0; hf < 2; hf++)
                reds[(wid & 3) * 64 + wrow + mt * 16 + hf * 8 + g] = l_run[mt][hf];
    }
    __syncthreads();

    #pragma unroll
    for (int mt = 0; mt < 2; mt++)
        #pragma unroll
        for (int hf = 0; hf < 2; hf++) {
            const int r = wrow + mt * 16 + hf * 8 + g;
            const float l_tot = reds[r] + reds[64 + r] + reds[128 + r] + reds[192 + r];
            const float inv = 1.0f / l_tot;
            const int row = q0 + r;
            __half* dst = attn + ((size_t)b * N_ + row) * DM + h * DH_;
            #pragma unroll
            for (int nt = 0; nt < 2; nt++) {
                const int d = wcol + nt * 8 + 2 * t;
                float v0 = o[mt][nt][hf * 2 + 0] * inv;
                float v1 = o[mt][nt][hf * 2 + 1] * inv;
                v0 = v0 > 0.f ? v0 : 0.01f * v0;
                v1 = v1 > 0.f ? v1 : 0.01f * v1;
                __half2 hv = __floats2half2_rn(v0, v1);
                *reinterpret_cast<__half2*>(dst + d) = hv;
            }
        }
}

// ---------------------------------------------------------------------------
// fp16 mma GEMM (BM=128, BN=64): 4 warps, warp tile 64x32, BK=64, 2-stage.
// ---------------------------------------------------------------------------
template<int EPI>
__global__ void __launch_bounds__(128, 4)
tc_gemm(const __half* __restrict__ A, const __half* __restrict__ Bw,
        const float* __restrict__ bias, void* __restrict__ Cv,
        int M, int N, int K,
        const float* __restrict__ e1)
{
    constexpr int THREADS = 128;
    constexpr int STG = (128 + 64) * LDW;

    extern __shared__ uint32_t sw[];

    const int tid  = threadIdx.x;
    const int wid  = tid >> 5;
    const int lane = tid & 31;
    const int g    = lane >> 2;
    const int t    = lane & 3;
    const int lrow = lane & 7, quad = lane >> 3;
    const int wr   = (wid >> 1) * 64;
    const int wc   = (wid & 1) * 32;

    const int brow = blockIdx.y * 128;
    const int bcol = blockIdx.x * 64;
    const __half* Ab = A  + (size_t)brow * K;
    const __half* Bb = Bw + (size_t)bcol * K;

    float c[4][4][4];
    #pragma unroll
    for (int i = 0; i < 4; i++)
        #pragma unroll
        for (int j = 0; j < 4; j++)
            #pragma unroll
            for (int r = 0; r < 4; r++) c[i][j][r] = 0.0f;

    const uint32_t smb = smem_u32(sw);
    const uint32_t a_pat = (uint32_t)(((quad & 1) * 8 + lrow) * LDW + (quad >> 1) * 4);
    const uint32_t b_pat = (uint32_t)(((quad >> 1) * 8 + lrow) * LDW + (quad & 1) * 4);

    auto load_stage = [&](int s) {
        const int buf = s & 1;
        const uint32_t as = smb + (uint32_t)(buf * STG) * 4u;
        const uint32_t bs = as + 128u * LDW * 4u;
        const __half* ag = Ab + s * 64;
        #pragma unroll
        for (int i = tid; i < 128 * 8; i += THREADS) {
            const int r = i >> 3, q = i & 7;
            CP_ASYNC16(as + (uint32_t)(r * LDW + q * 4) * 4u,
                       ag + (size_t)r * K + q * 8);
        }
        const __half* bg = Bb + s * 64;
        #pragma unroll
        for (int i = tid; i < 64 * 8; i += THREADS) {
            const int r = i >> 3, q = i & 7;
            CP_ASYNC16(bs + (uint32_t)(r * LDW + q * 4) * 4u,
                       bg + (size_t)r * K + q * 8);
        }
        CP_COMMIT();
    };

    const int S = K / 64;
    load_stage(0);

    for (int s = 0; s < S; s++) {
        if (s + 1 < S) { load_stage(s + 1); cp_wait<1>(); }
        else           { cp_wait<0>(); }
        __syncthreads();

        const int buf = s & 1;
        const uint32_t abase = smb + (uint32_t)(buf * STG) * 4u;
        const uint32_t bbase = abase + 128u * LDW * 4u;

        #pragma unroll
        for (int ks = 0; ks < 4; ks++) {
            const int kb = ks * 8;
            uint32_t af[4][4];
            #pragma unroll
            for (int mt = 0; mt < 4; mt++)
                LDSM_X4(af[mt][0], af[mt][1], af[mt][2], af[mt][3],
                        abase + (uint32_t)((wr + mt * 16) * LDW + kb + a_pat) * 4u);
            uint32_t bf[4][2];
            #pragma unroll
            for (int np = 0; np < 2; np++)
                LDSM_X4(bf[2 * np][0], bf[2 * np][1], bf[2 * np + 1][0], bf[2 * np + 1][1],
                        bbase + (uint32_t)((wc + np * 16) * LDW + kb + b_pat) * 4u);
            #pragma unroll
            for (int mt = 0; mt < 4; mt++)
                #pragma unroll
                for (int nt = 0; nt < 4; nt++)
                    mma_f16(c[mt][nt][0], c[mt][nt][1], c[mt][nt][2], c[mt][nt][3],
                            af[mt][0], af[mt][1], af[mt][2], af[mt][3],
                            bf[nt][0], bf[nt][1]);
        }
        __syncthreads();
    }

    #pragma unroll
    for (int mt = 0; mt < 4; mt++) {
        #pragma unroll
        for (int half = 0; half < 2; half++) {
            const int row = brow + wr + mt * 16 + g + half * 8;
            #pragma unroll
            for (int nt = 0; nt < 4; nt++) {
                const int col = bcol + wc + nt * 8 + 2 * t;
                float v0 = c[mt][nt][half * 2 + 0];
                float v1 = c[mt][nt][half * 2 + 1];
                if constexpr (EPI == 1) {
                    v0 += bias[col]; v1 += bias[col + 1];
                    const int h  = col / (3 * DH_);
                    const int cc = col % (3 * DH_);
                    const int bb = row >> 10;
                    const int n  = row & (N_ - 1);
                    if (cc < DH_) {
                        __half* base = g_hvT + ((size_t)(bb * H_ + h) * DH_ + cc) * N_ + n;
                        base[0]  = __float2half(v0);
                        base[N_] = __float2half(v1);
                    } else if (cc < 2 * DH_) {
                        *reinterpret_cast<__half2*>(
                            g_hq + ((size_t)(bb * H_ + h) * N_ + n) * DH_ + (cc - DH_)) =
                            __floats2half2_rn(v0, v1);
                    } else {
                        *reinterpret_cast<__half2*>(
                            g_hk + ((size_t)(bb * H_ + h) * N_ + n) * DH_ + (cc - 2 * DH_)) =
                            __floats2half2_rn(v0, v1);
                    }
                } else if constexpr (EPI == 4) {
                    float* C = (float*)Cv;
                    if (bias) { v0 += bias[col]; v1 += bias[col + 1]; }
                    float2 r2 = *reinterpret_cast<const float2*>(e1 + (size_t)row * N + col);
                    *reinterpret_cast<float2*>(C + (size_t)row * N + col) =
                        make_float2(v0 + r2.x, v1 + r2.y);
                } else {  // EPI 5
                    __half* C = (__half*)Cv;
                    v0 += bias[col]; v1 += bias[col + 1];
                    *reinterpret_cast<__half2*>(C + (size_t)row * N + col) =
                        __floats2half2_rn(fmaxf(v0, 0.f), fmaxf(v1, 0.f));
                }
            }
        }
    }
}

// ---------------------------------------------------------------------------
// Small-CTA fp16 GEMM (BM=64, BN=64): 2 warps (64 thr), warp tile 64x32,
// BK=64, 2-stage. Doubles grid for the starved GEMMs (Wo, MLP2).
//   EPI 4: +bias? +residual(e1) -> fp32 C
// ---------------------------------------------------------------------------
__global__ void __launch_bounds__(64, 6)
tc_gemm64(const __half* __restrict__ A, const __half* __restrict__ Bw,
          const float* __restrict__ bias, float* __restrict__ C,
          int M, int N, int K,
          const float* __restrict__ e1)
{
    constexpr int THREADS = 64;
    constexpr int STG = (64 + 64) * LDW;

    extern __shared__ uint32_t sw[];

    const int tid  = threadIdx.x;
    const int wid  = tid >> 5;
    const int lane = tid & 31;
    const int g    = lane >> 2;
    const int t    = lane & 3;
    const int lrow = lane & 7, quad = lane >> 3;
    const int wc   = wid * 32;            // warp cols: 0 or 32

    const int brow = blockIdx.y * 64;
    const int bcol = blockIdx.x * 64;
    const __half* Ab = A  + (size_t)brow * K;
    const __half* Bb = Bw + (size_t)bcol * K;

    float c[4][4][4];
    #pragma unroll
    for (int i = 0; i < 4; i++)
        #pragma unroll
        for (int j = 0; j < 4; j++)
            #pragma unroll
            for (int r = 0; r < 4; r++) c[i][j][r] = 0.0f;

    const uint32_t smb = smem_u32(sw);
    const uint32_t a_pat = (uint32_t)(((quad & 1) * 8 + lrow) * LDW + (quad >> 1) * 4);
    const uint32_t b_pat = (uint32_t)(((quad >> 1) * 8 + lrow) * LDW + (quad & 1) * 4);

    auto load_stage = [&](int s) {
        const int buf = s & 1;
        const uint32_t as = smb + (uint32_t)(buf * STG) * 4u;
        const uint32_t bs = as + 64u * LDW * 4u;
        const __half* ag = Ab + s * 64;
        #pragma unroll
        for (int i = tid; i < 64 * 8; i += THREADS) {
            const int r = i >> 3, q = i & 7;
            CP_ASYNC16(as + (uint32_t)(r * LDW + q * 4) * 4u,
                       ag + (size_t)r * K + q * 8);
        }
        const __half* bg = Bb + s * 64;
        #pragma unroll
        for (int i = tid; i < 64 * 8; i += THREADS) {
            const int r = i >> 3, q = i & 7;
            CP_ASYNC16(bs + (uint32_t)(r * LDW + q * 4) * 4u,
                       bg + (size_t)r * K + q * 8);
        }
        CP_COMMIT();
    };

    const int S = K / 64;
    load_stage(0);

    for (int s = 0; s < S; s++) {
        if (s + 1 < S) { load_stage(s + 1); cp_wait<1>(); }
        else           { cp_wait<0>(); }
        __syncthreads();

        const int buf = s & 1;
        const uint32_t abase = smb + (uint32_t)(buf * STG) * 4u;
        const uint32_t bbase = abase + 64u * LDW * 4u;

        #pragma unroll
        for (int ks = 0; ks < 4; ks++) {
            const int kb = ks * 8;
            uint32_t af[4][4];
            #pragma unroll
            for (int mt = 0; mt < 4; mt++)
                LDSM_X4(af[mt][0], af[mt][1], af[mt][2], af[mt][3],
                        abase + (uint32_t)((mt * 16) * LDW + kb + a_pat) * 4u);
            uint32_t bf[4][2];
            #pragma unroll
            for (int np = 0; np < 2; np++)
                LDSM_X4(bf[2 * np][0], bf[2 * np][1], bf[2 * np + 1][0], bf[2 * np + 1][1],
                        bbase + (uint32_t)((wc + np * 16) * LDW + kb + b_pat) * 4u);
            #pragma unroll
            for (int mt = 0; mt < 4; mt++)
                #pragma unroll
                for (int nt = 0; nt < 4; nt++)
                    mma_f16(c[mt][nt][0], c[mt][nt][1], c[mt][nt][2], c[mt][nt][3],
                            af[mt][0], af[mt][1], af[mt][2], af[mt][3],
                            bf[nt][0], bf[nt][1]);
        }
        __syncthreads();
    }

    #pragma unroll
    for (int mt = 0; mt < 4; mt++) {
        #pragma unroll
        for (int half = 0; half < 2; half++) {
            const int row = brow + mt * 16 + g + half * 8;
            #pragma unroll
            for (int nt = 0; nt < 4; nt++) {
                const int col = bcol + wc + nt * 8 + 2 * t;
                float v0 = c[mt][nt][half * 2 + 0];
                float v1 = c[mt][nt][half * 2 + 1];
                if (bias) { v0 += bias[col]; v1 += bias[col + 1]; }
                float2 r2 = *reinterpret_cast<const float2*>(e1 + (size_t)row * N + col);
                *reinterpret_cast<float2*>(C + (size_t)row * N + col) =
                    make_float2(v0 + r2.x, v1 + r2.y);
            }
        }
    }
}

// ---------------------------------------------------------------------------
// Launch
// ---------------------------------------------------------------------------
extern "C" void kernel_launch(void* const* d_in, const int* in_sizes, int n_in,
                              void* d_out, int out_size)
{
    const float* Z        = (const float*)d_in[0];
    const float* Dm       = (const float*)d_in[1];
    const float* new_mask = (const float*)d_in[2];
    const float* mask     = (const float*)d_in[3];
    const float* Wqkv     = (const float*)d_in[4];
    const float* bqkv     = (const float*)d_in[5];
    const float* Wo       = (const float*)d_in[6];
    const float* g1       = (const float*)d_in[7];
    const float* b1       = (const float*)d_in[8];
    const float* g2       = (const float*)d_in[9];
    const float* b2       = (const float*)d_in[10];
    const float* Wp1      = (const float*)d_in[11];
    const float* bp1      = (const float*)d_in[12];
    const float* Wp2      = (const float*)d_in[13];
    const float* bp2      = (const float*)d_in[14];
    const float* gamma    = (const float*)d_in[15];
    float* out = (float*)d_out;

    __half *pZnh, *pattnh, *pZn2h, *pHidh, *phWqkv, *phWo, *phWp1, *phWp2;
    float *pZ2;
    cudaGetSymbolAddress((void**)&pZnh,   g_Znh);
    cudaGetSymbolAddress((void**)&pattnh, g_attnh);
    cudaGetSymbolAddress((void**)&pZ2,    g_Z2);
    cudaGetSymbolAddress((void**)&pZn2h,  g_Zn2h);
    cudaGetSymbolAddress((void**)&pHidh,  g_Hidh);
    cudaGetSymbolAddress((void**)&phWqkv, g_hWqkv);
    cudaGetSymbolAddress((void**)&phWo,   g_hWo);
    cudaGetSymbolAddress((void**)&phWp1,  g_hWp1);
    cudaGetSymbolAddress((void**)&phWp2,  g_hWp2);

    const int SMG   = 2 * (128 + 64) * LDW * 4;   // 55296
    const int SMG64 = 2 * (64 + 64) * LDW * 4;    // 36864
    const int SMATT = SMATT_W * 4;                // 91136
    cudaFuncSetAttribute(tc_gemm<1>, cudaFuncAttributeMaxDynamicSharedMemorySize, SMG);
    cudaFuncSetAttribute(tc_gemm<5>, cudaFuncAttributeMaxDynamicSharedMemorySize, SMG);
    cudaFuncSetAttribute(tc_gemm64,  cudaFuncAttributeMaxDynamicSharedMemorySize, SMG64);
    cudaFuncSetAttribute(attn_kernel, cudaFuncAttributeMaxDynamicSharedMemorySize, SMATT);

    // 0) fused prep: weights -> fp16 + packed bias/mask
    prep_all<<<(NW4 + NBM4 + 255)/256, 256>>>(Wqkv, Wo, Wp1, Wp2,
                                              new_mask, Dm, mask, gamma);

    // 1) LN1 -> fp16
    ln_kernel<<<MROWS, 128>>>(Z, g1, b1, pZnh);

    // 2) QKV -> fp16 q/k/vT (24x32 = 768 CTAs)
    tc_gemm<1><<<dim3(QKV3/64, MROWS/128), 128, SMG>>>(
        pZnh, phWqkv, bqkv, nullptr, MROWS, QKV3, DM, nullptr);

    // 3) Flash attention -> fp16 attn
    attn_kernel<<<dim3(N_/64, B_*H_), 256, SMATT>>>(pattnh);

    // 4) Wo + residual -> fp32 Z2 (small CTA: 8x64 = 512 CTAs)
    tc_gemm64<<<dim3(DM/64, MROWS/64), 64, SMG64>>>(
        pattnh, phWo, nullptr, pZ2, MROWS, DM, DM, Z);

    // 5) LN2 -> fp16
    ln_kernel<<<MROWS, 128>>>(pZ2, g2, b2, pZn2h);

    // 6) MLP1 + relu -> fp16 Hid (32x32 = 1024 CTAs)
    tc_gemm<5><<<dim3(DI/64, MROWS/128), 128, SMG>>>(
        pZn2h, phWp1, bp1, pHidh, MROWS, DI, DM, nullptr);

    // 7) MLP2 + bias + residual -> fp32 out (small CTA: 8x64 = 512 CTAs)
    tc_gemm64<<<dim3(DM/64, MROWS/64), 64, SMG64>>>(
        pHidh, phWp2, bp2, out, MROWS, DM, DI, pZ2);
}

// round 16
// speedup vs baseline: 1.1880x; 1.0755x over previous
#include <cuda_runtime.h>
#include <cuda_fp16.h>
#include <cstdint>
#include <math.h>

#define B_   4
#define N_   1024
#define DM   512
#define H_   8
#define DH_  64
#define DI   2048
#define MROWS (B_*N_)          // 4096
#define QKV3 (3*DM)            // 1536

// ---------------------------------------------------------------------------
// Scratch (device globals)
// ---------------------------------------------------------------------------
__device__ __half g_Znh [MROWS*DM];
__device__ __half g_hq  [B_*H_*N_*DH_];
__device__ __half g_hk  [B_*H_*N_*DH_];
__device__ __half g_hvT [B_*H_*DH_*N_];
__device__ __half g_attnh[MROWS*DM];
__device__ float  g_Z2  [MROWS*DM];
__device__ __half g_Zn2h[MROWS*DM];
__device__ __half g_Hidh[MROWS*DI];
__device__ __half g_hWqkv[QKV3*DM];
__device__ __half g_hWo [DM*DM];
__device__ __half g_hWp1[DI*DM];
__device__ __half g_hWp2[DM*DI];
__device__ uint32_t g_bm[(size_t)B_*N_*N_];   // packed half2(nm - gamma*D, mask)

// ---------------------------------------------------------------------------
// Helpers
// ---------------------------------------------------------------------------
__device__ __forceinline__ uint32_t smem_u32(const void* p) {
    uint32_t a;
    asm("{ .reg .u64 t; cvta.to.shared.u64 t, %1; cvt.u32.u64 %0, t; }" : "=r"(a) : "l"(p));
    return a;
}
#define CP_ASYNC16(sa, ga) \
    asm volatile("cp.async.cg.shared.global [%0], [%1], 16;" :: "r"(sa), "l"(ga))
#define CP_COMMIT() asm volatile("cp.async.commit_group;" ::: "memory")
template<int Nw> __device__ __forceinline__ void cp_wait() {
    asm volatile("cp.async.wait_group %0;" :: "n"(Nw) : "memory");
}
#define LDSM_X4(r0, r1, r2, r3, addr) \
    asm volatile("ldmatrix.sync.aligned.m8n8.x4.shared.b16 {%0,%1,%2,%3}, [%4];" \
        : "=r"(r0), "=r"(r1), "=r"(r2), "=r"(r3) : "r"(addr))
__device__ __forceinline__ void mma_f16(float& c0, float& c1, float& c2, float& c3,
                                        uint32_t a0, uint32_t a1, uint32_t a2, uint32_t a3,
                                        uint32_t b0, uint32_t b1) {
    asm volatile(
        "mma.sync.aligned.m16n8k16.row.col.f32.f16.f16.f32 "
        "{%0,%1,%2,%3},{%4,%5,%6,%7},{%8,%9},{%0,%1,%2,%3};"
        : "+f"(c0), "+f"(c1), "+f"(c2), "+f"(c3)
        : "r"(a0), "r"(a1), "r"(a2), "r"(a3), "r"(b0), "r"(b1));
}

// ---------------------------------------------------------------------------
// Fused prep: fp32->fp16 weights + packed bias/mask, one launch.
// ---------------------------------------------------------------------------
#define Q0 (QKV3*DM/4)
#define Q1 (DM*DM/4)
#define Q2 (DI*DM/4)
#define Q3 (DM*DI/4)
#define NW4 (Q0+Q1+Q2+Q3)
#define NBM4 ((B_*N_*N_)/4)
__global__ void prep_all(const float* __restrict__ w0, const float* __restrict__ w1,
                         const float* __restrict__ w2, const float* __restrict__ w3,
                         const float* __restrict__ nm, const float* __restrict__ D,
                         const float* __restrict__ mask, const float* __restrict__ gptr)
{
    int i = blockIdx.x * 256 + threadIdx.x;
    if (i < NW4) {
        const float* s; __half* d;
        if (i < Q0)                { s = w0; d = g_hWqkv; }
        else if ((i -= Q0) < Q1)   { s = w1; d = g_hWo; }
        else if ((i -= Q1) < Q2)   { s = w2; d = g_hWp1; }
        else           { i -= Q2;    s = w3; d = g_hWp2; }
        float4 v = reinterpret_cast<const float4*>(s)[i];
        reinterpret_cast<__half2*>(d)[2 * i]     = __floats2half2_rn(v.x, v.y);
        reinterpret_cast<__half2*>(d)[2 * i + 1] = __floats2half2_rn(v.z, v.w);
        return;
    }
    i -= NW4;
    if (i >= NBM4) return;
    const float g = gptr[0];
    float4 a = reinterpret_cast<const float4*>(nm)[i];
    float4 d4 = reinterpret_cast<const float4*>(D)[i];
    float4 m = reinterpret_cast<const float4*>(mask)[i];
    uint32_t* o = g_bm + 4 * (size_t)i;
    __half2 h0 = __floats2half2_rn(a.x - g * d4.x, m.x);
    __half2 h1 = __floats2half2_rn(a.y - g * d4.y, m.y);
    __half2 h2 = __floats2half2_rn(a.z - g * d4.z, m.z);
    __half2 h3 = __floats2half2_rn(a.w - g * d4.w, m.w);
    o[0] = *reinterpret_cast<uint32_t*>(&h0);
    o[1] = *reinterpret_cast<uint32_t*>(&h1);
    o[2] = *reinterpret_cast<uint32_t*>(&h2);
    o[3] = *reinterpret_cast<uint32_t*>(&h3);
}

// ---------------------------------------------------------------------------
// LayerNorm: fp32 in -> fp16 out
// ---------------------------------------------------------------------------
__global__ void ln_kernel(const float* __restrict__ X,
                          const float* __restrict__ g,
                          const float* __restrict__ b,
                          __half* __restrict__ Y)
{
    const int row = blockIdx.x;
    const int tid = threadIdx.x;
    const float4* x4 = reinterpret_cast<const float4*>(X + (size_t)row * DM);
    float4 v = x4[tid];
    float s  = v.x + v.y + v.z + v.w;
    float ss = v.x*v.x + v.y*v.y + v.z*v.z + v.w*v.w;
    #pragma unroll
    for (int o = 16; o; o >>= 1) {
        s  += __shfl_xor_sync(0xffffffffu, s,  o);
        ss += __shfl_xor_sync(0xffffffffu, ss, o);
    }
    __shared__ float sh_s[4], sh_ss[4];
    if ((tid & 31) == 0) { sh_s[tid >> 5] = s; sh_ss[tid >> 5] = ss; }
    __syncthreads();
    s  = sh_s[0]  + sh_s[1]  + sh_s[2]  + sh_s[3];
    ss = sh_ss[0] + sh_ss[1] + sh_ss[2] + sh_ss[3];
    const float mu  = s * (1.0f / DM);
    const float var = ss * (1.0f / DM) - mu * mu;
    const float r   = rsqrtf(var + 1e-5f);
    const float4 gv = reinterpret_cast<const float4*>(g)[tid];
    const float4 bv = reinterpret_cast<const float4*>(b)[tid];
    __half2 h0 = __floats2half2_rn((v.x - mu) * r * gv.x + bv.x,
                                   (v.y - mu) * r * gv.y + bv.y);
    __half2 h1 = __floats2half2_rn((v.z - mu) * r * gv.z + bv.z,
                                   (v.w - mu) * r * gv.w + bv.w);
    __half2* y2 = reinterpret_cast<__half2*>(Y + (size_t)row * DM);
    y2[2 * tid]     = h0;
    y2[2 * tid + 1] = h1;
}

// ---------------------------------------------------------------------------
// Fused flash attention, register-resident P (FA2 layout trick).
// 128 threads = 4 warps; warp w owns rows [16w,16w+16) x all 64 cols.
// No P smem round-trip, no cross-warp reductions, 1 sync/iter.
// ---------------------------------------------------------------------------
#define LDW  36
#define LBM  68
#define KS_OFF  2304
#define VT_OFF  6912
#define BM_OFF  11520
#define SMATT_W 20224
__global__ void __launch_bounds__(128, 2)
attn_kernel(__half* __restrict__ attn)
{
    extern __shared__ uint32_t sw[];

    const int tid = threadIdx.x, lane = tid & 31, wid = tid >> 5;
    const int g = lane >> 2, t = lane & 3;
    const int lrow = lane & 7, quad = lane >> 3;
    const int wrow = wid * 16;
    const int bh = blockIdx.y, b = bh >> 3, h = bh & 7;
    const int q0 = blockIdx.x * 64;

    const __half* qg = g_hq + ((size_t)bh * N_ + q0) * DH_;
    const __half* kg = g_hk + (size_t)bh * N_ * DH_;
    const __half* vg = g_hvT + (size_t)bh * DH_ * N_;
    const uint32_t* bmg = g_bm + ((size_t)b * N_ + q0) * N_;

    const uint32_t swb = smem_u32(sw);
    const uint32_t a_pat = (uint32_t)(((quad & 1) * 8 + lrow) * LDW + (quad >> 1) * 4);
    const uint32_t b_pat = (uint32_t)(((quad >> 1) * 8 + lrow) * LDW + (quad & 1) * 4);

    auto load_kvbm = [&](int it) {
        const int buf = it & 1;
        const uint32_t ks_a = swb + (KS_OFF + buf * 2304) * 4u;
        const uint32_t vt_a = swb + (VT_OFF + buf * 2304) * 4u;
        const uint32_t bm_a = swb + (BM_OFF + buf * 4352) * 4u;
        #pragma unroll
        for (int i = tid; i < 64 * 8; i += 128) {
            const int r = i >> 3, q = i & 7;
            CP_ASYNC16(ks_a + (uint32_t)(r * LDW + q * 4) * 4u,
                       kg + (size_t)(it * 64 + r) * DH_ + q * 8);
        }
        #pragma unroll
        for (int i = tid; i < 64 * 8; i += 128) {
            const int r = i >> 3, q = i & 7;
            CP_ASYNC16(vt_a + (uint32_t)(r * LDW + q * 4) * 4u,
                       vg + (size_t)r * N_ + it * 64 + q * 8);
        }
        #pragma unroll
        for (int i = tid; i < 64 * 16; i += 128) {
            const int r = i >> 4, q = i & 15;
            CP_ASYNC16(bm_a + (uint32_t)(r * LBM + q * 4) * 4u,
                       bmg + (size_t)r * N_ + it * 64 + q * 4);
        }
        CP_COMMIT();
    };

    // Q tile load + stage 0
    #pragma unroll
    for (int i = tid; i < 64 * 8; i += 128) {
        const int r = i >> 3, q = i & 7;
        CP_ASYNC16(swb + (uint32_t)(r * LDW + q * 4) * 4u, qg + (size_t)r * DH_ + q * 8);
    }
    load_kvbm(0);

    float l_run[2] = {0.f, 0.f};
    float o[8][4];
    #pragma unroll
    for (int j = 0; j < 8; j++)
        #pragma unroll
        for (int r = 0; r < 4; r++) o[j][r] = 0.f;

    const float LN16 = 2.772588722f;

    for (int it = 0; it < 16; it++) {
        cp_wait<0>();
        __syncthreads();
        if (it + 1 < 16) load_kvbm(it + 1);

        const int buf = it & 1;
        const uint32_t ks_a = swb + (KS_OFF + buf * 2304) * 4u;
        const uint32_t vt_a = swb + (VT_OFF + buf * 2304) * 4u;
        const uint32_t* bms = sw + BM_OFF + buf * 4352;

        // S = Q @ K^T : warp strip 16 x 64 (8 n8 tiles)
        float s[8][4];
        #pragma unroll
        for (int j = 0; j < 8; j++)
            #pragma unroll
            for (int r = 0; r < 4; r++) s[j][r] = 0.f;
        #pragma unroll
        for (int kk = 0; kk < 4; kk++) {
            const int kb = kk * 8;
            uint32_t qa[4], bf[8][2];
            LDSM_X4(qa[0], qa[1], qa[2], qa[3],
                    swb + (uint32_t)(wrow * LDW + kb + a_pat) * 4u);
            #pragma unroll
            for (int n2 = 0; n2 < 4; n2++)
                LDSM_X4(bf[2 * n2][0], bf[2 * n2][1], bf[2 * n2 + 1][0], bf[2 * n2 + 1][1],
                        ks_a + (uint32_t)((n2 * 16) * LDW + kb + b_pat) * 4u);
            #pragma unroll
            for (int nt = 0; nt < 8; nt++)
                mma_f16(s[nt][0], s[nt][1], s[nt][2], s[nt][3],
                        qa[0], qa[1], qa[2], qa[3], bf[nt][0], bf[nt][1]);
        }

        // bias + exp + mask -> pack P into A-fragment registers
        uint32_t pa[4][4];
        #pragma unroll
        for (int nt = 0; nt < 8; nt++) {
            #pragma unroll
            for (int hf = 0; hf < 2; hf++) {
                const int rl = wrow + hf * 8 + g;
                const int cl = nt * 8 + 2 * t;
                uint2 w = *reinterpret_cast<const uint2*>(bms + rl * LBM + cl);
                __half2 h0 = *reinterpret_cast<__half2*>(&w.x);
                __half2 h1 = *reinterpret_cast<__half2*>(&w.y);
                float x0 = fmaf(s[nt][hf * 2 + 0], 0.125f, __half2float(__low2half(h0)));
                float x1 = fmaf(s[nt][hf * 2 + 1], 0.125f, __half2float(__low2half(h1)));
                float e0 = __expf(x0 - LN16);
                float e1 = __expf(x1 - LN16);
                l_run[hf] += e0 + e1;
                __half2 ev = __floats2half2_rn(e0, e1);
                __half2 mm = __halves2half2(__high2half(h0), __high2half(h1));
                __half2 pv = __hmul2(ev, mm);
                pa[nt >> 1][2 * (nt & 1) + hf] = *reinterpret_cast<uint32_t*>(&pv);
            }
        }

        // O += P @ V  (P A-fragments in registers; V B-fragments from smem)
        #pragma unroll
        for (int kc = 0; kc < 4; kc++) {
            uint32_t vbf[8][2];
            #pragma unroll
            for (int n2 = 0; n2 < 4; n2++)
                LDSM_X4(vbf[2 * n2][0], vbf[2 * n2][1], vbf[2 * n2 + 1][0], vbf[2 * n2 + 1][1],
                        vt_a + (uint32_t)((n2 * 16) * LDW + kc * 8 + b_pat) * 4u);
            #pragma unroll
            for (int j = 0; j < 8; j++)
                mma_f16(o[j][0], o[j][1], o[j][2], o[j][3],
                        pa[kc][0], pa[kc][1], pa[kc][2], pa[kc][3],
                        vbf[j][0], vbf[j][1]);
        }
    }

    // Row sums: each warp owns its rows; quad shuffle only.
    #pragma unroll
    for (int x = 1; x <= 2; x <<= 1)
        #pragma unroll
        for (int hf = 0; hf < 2; hf++)
            l_run[hf] += __shfl_xor_sync(0xffffffffu, l_run[hf], x);

    #pragma unroll
    for (int hf = 0; hf < 2; hf++) {
        const float inv = 1.0f / l_run[hf];
        const int row = q0 + wrow + hf * 8 + g;
        __half* dst = attn + ((size_t)b * N_ + row) * DM + h * DH_;
        #pragma unroll
        for (int j = 0; j < 8; j++) {
            const int d = j * 8 + 2 * t;
            float v0 = o[j][hf * 2 + 0] * inv;
            float v1 = o[j][hf * 2 + 1] * inv;
            v0 = v0 > 0.f ? v0 : 0.01f * v0;
            v1 = v1 > 0.f ? v1 : 0.01f * v1;
            __half2 hv = __floats2half2_rn(v0, v1);
            *reinterpret_cast<__half2*>(dst + d) = hv;
        }
    }
}

// ---------------------------------------------------------------------------
// fp16 mma GEMM (BM=128, BN=64): 4 warps, warp tile 64x32, BK=64, 2-stage.
// ---------------------------------------------------------------------------
template<int EPI>
__global__ void __launch_bounds__(128, 4)
tc_gemm(const __half* __restrict__ A, const __half* __restrict__ Bw,
        const float* __restrict__ bias, void* __restrict__ Cv,
        int M, int N, int K,
        const float* __restrict__ e1)
{
    constexpr int THREADS = 128;
    constexpr int STG = (128 + 64) * LDW;

    extern __shared__ uint32_t sw[];

    const int tid  = threadIdx.x;
    const int wid  = tid >> 5;
    const int lane = tid & 31;
    const int g    = lane >> 2;
    const int t    = lane & 3;
    const int lrow = lane & 7, quad = lane >> 3;
    const int wr   = (wid >> 1) * 64;
    const int wc   = (wid & 1) * 32;

    const int brow = blockIdx.y * 128;
    const int bcol = blockIdx.x * 64;
    const __half* Ab = A  + (size_t)brow * K;
    const __half* Bb = Bw + (size_t)bcol * K;

    float c[4][4][4];
    #pragma unroll
    for (int i = 0; i < 4; i++)
        #pragma unroll
        for (int j = 0; j < 4; j++)
            #pragma unroll
            for (int r = 0; r < 4; r++) c[i][j][r] = 0.0f;

    const uint32_t smb = smem_u32(sw);
    const uint32_t a_pat = (uint32_t)(((quad & 1) * 8 + lrow) * LDW + (quad >> 1) * 4);
    const uint32_t b_pat = (uint32_t)(((quad >> 1) * 8 + lrow) * LDW + (quad & 1) * 4);

    auto load_stage = [&](int s) {
        const int buf = s & 1;
        const uint32_t as = smb + (uint32_t)(buf * STG) * 4u;
        const uint32_t bs = as + 128u * LDW * 4u;
        const __half* ag = Ab + s * 64;
        #pragma unroll
        for (int i = tid; i < 128 * 8; i += THREADS) {
            const int r = i >> 3, q = i & 7;
            CP_ASYNC16(as + (uint32_t)(r * LDW + q * 4) * 4u,
                       ag + (size_t)r * K + q * 8);
        }
        const __half* bg = Bb + s * 64;
        #pragma unroll
        for (int i = tid; i < 64 * 8; i += THREADS) {
            const int r = i >> 3, q = i & 7;
            CP_ASYNC16(bs + (uint32_t)(r * LDW + q * 4) * 4u,
                       bg + (size_t)r * K + q * 8);
        }
        CP_COMMIT();
    };

    const int S = K / 64;
    load_stage(0);

    for (int s = 0; s < S; s++) {
        if (s + 1 < S) { load_stage(s + 1); cp_wait<1>(); }
        else           { cp_wait<0>(); }
        __syncthreads();

        const int buf = s & 1;
        const uint32_t abase = smb + (uint32_t)(buf * STG) * 4u;
        const uint32_t bbase = abase + 128u * LDW * 4u;

        #pragma unroll
        for (int ks = 0; ks < 4; ks++) {
            const int kb = ks * 8;
            uint32_t af[4][4];
            #pragma unroll
            for (int mt = 0; mt < 4; mt++)
                LDSM_X4(af[mt][0], af[mt][1], af[mt][2], af[mt][3],
                        abase + (uint32_t)((wr + mt * 16) * LDW + kb + a_pat) * 4u);
            uint32_t bf[4][2];
            #pragma unroll
            for (int np = 0; np < 2; np++)
                LDSM_X4(bf[2 * np][0], bf[2 * np][1], bf[2 * np + 1][0], bf[2 * np + 1][1],
                        bbase + (uint32_t)((wc + np * 16) * LDW + kb + b_pat) * 4u);
            #pragma unroll
            for (int mt = 0; mt < 4; mt++)
                #pragma unroll
                for (int nt = 0; nt < 4; nt++)
                    mma_f16(c[mt][nt][0], c[mt][nt][1], c[mt][nt][2], c[mt][nt][3],
                            af[mt][0], af[mt][1], af[mt][2], af[mt][3],
                            bf[nt][0], bf[nt][1]);
        }
        __syncthreads();
    }

    #pragma unroll
    for (int mt = 0; mt < 4; mt++) {
        #pragma unroll
        for (int half = 0; half < 2; half++) {
            const int row = brow + wr + mt * 16 + g + half * 8;
            #pragma unroll
            for (int nt = 0; nt < 4; nt++) {
                const int col = bcol + wc + nt * 8 + 2 * t;
                float v0 = c[mt][nt][half * 2 + 0];
                float v1 = c[mt][nt][half * 2 + 1];
                if constexpr (EPI == 1) {
                    v0 += bias[col]; v1 += bias[col + 1];
                    const int h  = col / (3 * DH_);
                    const int cc = col % (3 * DH_);
                    const int bb = row >> 10;
                    const int n  = row & (N_ - 1);
                    if (cc < DH_) {
                        __half* base = g_hvT + ((size_t)(bb * H_ + h) * DH_ + cc) * N_ + n;
                        base[0]  = __float2half(v0);
                        base[N_] = __float2half(v1);
                    } else if (cc < 2 * DH_) {
                        *reinterpret_cast<__half2*>(
                            g_hq + ((size_t)(bb * H_ + h) * N_ + n) * DH_ + (cc - DH_)) =
                            __floats2half2_rn(v0, v1);
                    } else {
                        *reinterpret_cast<__half2*>(
                            g_hk + ((size_t)(bb * H_ + h) * N_ + n) * DH_ + (cc - 2 * DH_)) =
                            __floats2half2_rn(v0, v1);
                    }
                } else if constexpr (EPI == 4) {
                    float* C = (float*)Cv;
                    if (bias) { v0 += bias[col]; v1 += bias[col + 1]; }
                    float2 r2 = *reinterpret_cast<const float2*>(e1 + (size_t)row * N + col);
                    *reinterpret_cast<float2*>(C + (size_t)row * N + col) =
                        make_float2(v0 + r2.x, v1 + r2.y);
                } else {  // EPI 5
                    __half* C = (__half*)Cv;
                    v0 += bias[col]; v1 += bias[col + 1];
                    *reinterpret_cast<__half2*>(C + (size_t)row * N + col) =
                        __floats2half2_rn(fmaxf(v0, 0.f), fmaxf(v1, 0.f));
                }
            }
        }
    }
}

// ---------------------------------------------------------------------------
// Small-CTA fp16 GEMM (BM=64, BN=64): 2 warps, warp tile 64x32, BK=64.
//   +bias? +residual(e1) -> fp32 C
// ---------------------------------------------------------------------------
__global__ void __launch_bounds__(64, 6)
tc_gemm64(const __half* __restrict__ A, const __half* __restrict__ Bw,
          const float* __restrict__ bias, float* __restrict__ C,
          int M, int N, int K,
          const float* __restrict__ e1)
{
    constexpr int THREADS = 64;
    constexpr int STG = (64 + 64) * LDW;

    extern __shared__ uint32_t sw[];

    const int tid  = threadIdx.x;
    const int wid  = tid >> 5;
    const int lane = tid & 31;
    const int g    = lane >> 2;
    const int t    = lane & 3;
    const int lrow = lane & 7, quad = lane >> 3;
    const int wc   = wid * 32;

    const int brow = blockIdx.y * 64;
    const int bcol = blockIdx.x * 64;
    const __half* Ab = A  + (size_t)brow * K;
    const __half* Bb = Bw + (size_t)bcol * K;

    float c[4][4][4];
    #pragma unroll
    for (int i = 0; i < 4; i++)
        #pragma unroll
        for (int j = 0; j < 4; j++)
            #pragma unroll
            for (int r = 0; r < 4; r++) c[i][j][r] = 0.0f;

    const uint32_t smb = smem_u32(sw);
    const uint32_t a_pat = (uint32_t)(((quad & 1) * 8 + lrow) * LDW + (quad >> 1) * 4);
    const uint32_t b_pat = (uint32_t)(((quad >> 1) * 8 + lrow) * LDW + (quad & 1) * 4);

    auto load_stage = [&](int s) {
        const int buf = s & 1;
        const uint32_t as = smb + (uint32_t)(buf * STG) * 4u;
        const uint32_t bs = as + 64u * LDW * 4u;
        const __half* ag = Ab + s * 64;
        #pragma unroll
        for (int i = tid; i < 64 * 8; i += THREADS) {
            const int r = i >> 3, q = i & 7;
            CP_ASYNC16(as + (uint32_t)(r * LDW + q * 4) * 4u,
                       ag + (size_t)r * K + q * 8);
        }
        const __half* bg = Bb + s * 64;
        #pragma unroll
        for (int i = tid; i < 64 * 8; i += THREADS) {
            const int r = i >> 3, q = i & 7;
            CP_ASYNC16(bs + (uint32_t)(r * LDW + q * 4) * 4u,
                       bg + (size_t)r * K + q * 8);
        }
        CP_COMMIT();
    };

    const int S = K / 64;
    load_stage(0);

    for (int s = 0; s < S; s++) {
        if (s + 1 < S) { load_stage(s + 1); cp_wait<1>(); }
        else           { cp_wait<0>(); }
        __syncthreads();

        const int buf = s & 1;
        const uint32_t abase = smb + (uint32_t)(buf * STG) * 4u;
        const uint32_t bbase = abase + 64u * LDW * 4u;

        #pragma unroll
        for (int ks = 0; ks < 4; ks++) {
            const int kb = ks * 8;
            uint32_t af[4][4];
            #pragma unroll
            for (int mt = 0; mt < 4; mt++)
                LDSM_X4(af[mt][0], af[mt][1], af[mt][2], af[mt][3],
                        abase + (uint32_t)((mt * 16) * LDW + kb + a_pat) * 4u);
            uint32_t bf[4][2];
            #pragma unroll
            for (int np = 0; np < 2; np++)
                LDSM_X4(bf[2 * np][0], bf[2 * np][1], bf[2 * np + 1][0], bf[2 * np + 1][1],
                        bbase + (uint32_t)((wc + np * 16) * LDW + kb + b_pat) * 4u);
            #pragma unroll
            for (int mt = 0; mt < 4; mt++)
                #pragma unroll
                for (int nt = 0; nt < 4; nt++)
                    mma_f16(c[mt][nt][0], c[mt][nt][1], c[mt][nt][2], c[mt][nt][3],
                            af[mt][0], af[mt][1], af[mt][2], af[mt][3],
                            bf[nt][0], bf[nt][1]);
        }
        __syncthreads();
    }

    #pragma unroll
    for (int mt = 0; mt < 4; mt++) {
        #pragma unroll
        for (int half = 0; half < 2; half++) {
            const int row = brow + mt * 16 + g + half * 8;
            #pragma unroll
            for (int nt = 0; nt < 4; nt++) {
                const int col = bcol + wc + nt * 8 + 2 * t;
                float v0 = c[mt][nt][half * 2 + 0];
                float v1 = c[mt][nt][half * 2 + 1];
                if (bias) { v0 += bias[col]; v1 += bias[col + 1]; }
                float2 r2 = *reinterpret_cast<const float2*>(e1 + (size_t)row * N + col);
                *reinterpret_cast<float2*>(C + (size_t)row * N + col) =
                    make_float2(v0 + r2.x, v1 + r2.y);
            }
        }
    }
}

// ---------------------------------------------------------------------------
// Launch
// ---------------------------------------------------------------------------
extern "C" void kernel_launch(void* const* d_in, const int* in_sizes, int n_in,
                              void* d_out, int out_size)
{
    const float* Z        = (const float*)d_in[0];
    const float* Dm       = (const float*)d_in[1];
    const float* new_mask = (const float*)d_in[2];
    const float* mask     = (const float*)d_in[3];
    const float* Wqkv     = (const float*)d_in[4];
    const float* bqkv     = (const float*)d_in[5];
    const float* Wo       = (const float*)d_in[6];
    const float* g1       = (const float*)d_in[7];
    const float* b1       = (const float*)d_in[8];
    const float* g2       = (const float*)d_in[9];
    const float* b2       = (const float*)d_in[10];
    const float* Wp1      = (const float*)d_in[11];
    const float* bp1      = (const float*)d_in[12];
    const float* Wp2      = (const float*)d_in[13];
    const float* bp2      = (const float*)d_in[14];
    const float* gamma    = (const float*)d_in[15];
    float* out = (float*)d_out;

    __half *pZnh, *pattnh, *pZn2h, *pHidh, *phWqkv, *phWo, *phWp1, *phWp2;
    float *pZ2;
    cudaGetSymbolAddress((void**)&pZnh,   g_Znh);
    cudaGetSymbolAddress((void**)&pattnh, g_attnh);
    cudaGetSymbolAddress((void**)&pZ2,    g_Z2);
    cudaGetSymbolAddress((void**)&pZn2h,  g_Zn2h);
    cudaGetSymbolAddress((void**)&pHidh,  g_Hidh);
    cudaGetSymbolAddress((void**)&phWqkv, g_hWqkv);
    cudaGetSymbolAddress((void**)&phWo,   g_hWo);
    cudaGetSymbolAddress((void**)&phWp1,  g_hWp1);
    cudaGetSymbolAddress((void**)&phWp2,  g_hWp2);

    const int SMG   = 2 * (128 + 64) * LDW * 4;   // 55296
    const int SMG64 = 2 * (64 + 64) * LDW * 4;    // 36864
    const int SMATT = SMATT_W * 4;                // 80896
    cudaFuncSetAttribute(tc_gemm<1>, cudaFuncAttributeMaxDynamicSharedMemorySize, SMG);
    cudaFuncSetAttribute(tc_gemm<5>, cudaFuncAttributeMaxDynamicSharedMemorySize, SMG);
    cudaFuncSetAttribute(tc_gemm64,  cudaFuncAttributeMaxDynamicSharedMemorySize, SMG64);
    cudaFuncSetAttribute(attn_kernel, cudaFuncAttributeMaxDynamicSharedMemorySize, SMATT);

    // 0) fused prep: weights -> fp16 + packed bias/mask
    prep_all<<<(NW4 + NBM4 + 255)/256, 256>>>(Wqkv, Wo, Wp1, Wp2,
                                              new_mask, Dm, mask, gamma);

    // 1) LN1 -> fp16
    ln_kernel<<<MROWS, 128>>>(Z, g1, b1, pZnh);

    // 2) QKV -> fp16 q/k/vT (768 CTAs)
    tc_gemm<1><<<dim3(QKV3/64, MROWS/128), 128, SMG>>>(
        pZnh, phWqkv, bqkv, nullptr, MROWS, QKV3, DM, nullptr);

    // 3) Flash attention (register P) -> fp16 attn (512 CTAs)
    attn_kernel<<<dim3(N_/64, B_*H_), 128, SMATT>>>(pattnh);

    // 4) Wo + residual -> fp32 Z2 (512 CTAs)
    tc_gemm64<<<dim3(DM/64, MROWS/64), 64, SMG64>>>(
        pattnh, phWo, nullptr, pZ2, MROWS, DM, DM, Z);

    // 5) LN2 -> fp16
    ln_kernel<<<MROWS, 128>>>(pZ2, g2, b2, pZn2h);

    // 6) MLP1 + relu -> fp16 Hid (1024 CTAs)
    tc_gemm<5><<<dim3(DI/64, MROWS/128), 128, SMG>>>(
        pZn2h, phWp1, bp1, pHidh, MROWS, DI, DM, nullptr);

    // 7) MLP2 + bias + residual -> fp32 out (512 CTAs)
    tc_gemm64<<<dim3(DM/64, MROWS/64), 64, SMG64>>>(
        pHidh, phWp2, bp2, out, MROWS, DM, DI, pZ2);
}